// round 2
// baseline (speedup 1.0000x reference)
#include <cuda_runtime.h>
#include <math.h>

#define BB 8
#define TT 512
#define DD 768
#define HH 12
#define DHH 64
#define FF 3072
#define LL 12
#define BT (BB*TT)      // 4096
#define ZZ (BB*HH)      // 96

// ---------------- scratch (device globals; no allocation) ----------------
__device__ float g_hbase[BT*DD];
__device__ float g_p[BT*2];
__device__ float g_s[BT];
__device__ float g_h[BT*DD];
__device__ float g_q[BT*DD];
__device__ float g_k[BT*DD];
__device__ float g_v[BT*DD];
__device__ float g_scores[(size_t)ZZ*TT*TT];   // 25.2M floats
__device__ float g_ctx[BT*DD];
__device__ float g_attnout[BT*DD];
__device__ float g_hmid[BT*DD];
__device__ float g_ffn1[(size_t)BT*FF];
__device__ float g_ffn2[BT*DD];

// ---------------- stage 1: h_base + language distribution p ----------------
__global__ void embed_base_kernel(const int* __restrict__ ids,
                                  const float* __restrict__ tok,
                                  const float* __restrict__ pos,
                                  const float* __restrict__ proto,
                                  const float* __restrict__ log_tau) {
    int row = blockIdx.x;
    int t = row % TT;
    int id = ids[row];
    const float* trow = tok + (size_t)id * DD;
    const float* prow = pos + (size_t)t * DD;
    float a0 = 0.f, a1 = 0.f;
    __shared__ float r0[256], r1[256];
    for (int d = threadIdx.x; d < DD; d += 256) {
        float v = trow[d] + prow[d];
        g_hbase[(size_t)row*DD + d] = v;
        a0 += v * proto[d];
        a1 += v * proto[DD + d];
    }
    r0[threadIdx.x] = a0; r1[threadIdx.x] = a1;
    __syncthreads();
    for (int s = 128; s > 0; s >>= 1) {
        if (threadIdx.x < s) {
            r0[threadIdx.x] += r0[threadIdx.x + s];
            r1[threadIdx.x] += r1[threadIdx.x + s];
        }
        __syncthreads();
    }
    if (threadIdx.x == 0) {
        float tau = fmaxf(expf(log_tau[0]), 0.25f);
        float l0 = r0[0] / tau, l1 = r1[0] / tau;
        float m = fmaxf(l0, l1);
        float e0 = expf(l0 - m), e1 = expf(l1 - m);
        float inv = 1.f / (e0 + e1);
        g_p[row*2 + 0] = e0 * inv;
        g_p[row*2 + 1] = e1 * inv;
    }
}

// ---------------- switch magnitude s ----------------
__global__ void switch_kernel() {
    int i = blockIdx.x * blockDim.x + threadIdx.x;
    if (i >= BT) return;
    int t = i % TT;
    float sv = 0.f;
    if (t > 0)
        sv = 1.f - (g_p[i*2]*g_p[(i-1)*2] + g_p[i*2+1]*g_p[(i-1)*2+1]);
    g_s[i] = sv;
}

// ---------------- embedding LN: h = LN(h_base + p@lang + s*switch) ----------------
__global__ void embed_ln_kernel(const float* __restrict__ lang,
                                const float* __restrict__ sw,
                                const float* __restrict__ w,
                                const float* __restrict__ b) {
    int row = blockIdx.x;
    __shared__ float xs[DD];
    __shared__ float rs[256], rq[256];
    float p0 = g_p[row*2], p1 = g_p[row*2+1], sv = g_s[row];
    float sum = 0.f, sq = 0.f;
    for (int d = threadIdx.x; d < DD; d += 256) {
        float x = g_hbase[(size_t)row*DD + d] + p0*lang[d] + p1*lang[DD+d] + sv*sw[d];
        xs[d] = x; sum += x; sq += x*x;
    }
    rs[threadIdx.x] = sum; rq[threadIdx.x] = sq;
    __syncthreads();
    for (int s = 128; s > 0; s >>= 1) {
        if (threadIdx.x < s) { rs[threadIdx.x]+=rs[threadIdx.x+s]; rq[threadIdx.x]+=rq[threadIdx.x+s]; }
        __syncthreads();
    }
    float mu = rs[0] * (1.f/DD);
    float var = rq[0] * (1.f/DD) - mu*mu;
    float rstd = rsqrtf(var + 1e-12f);
    for (int d = threadIdx.x; d < DD; d += 256)
        g_h[(size_t)row*DD + d] = (xs[d]-mu)*rstd*w[d] + b[d];
}

// ---------------- generic residual LN: out = LN(a+b)*w+bias ----------------
__global__ void ln_residual_kernel(const float* __restrict__ a,
                                   const float* __restrict__ bres,
                                   const float* __restrict__ w,
                                   const float* __restrict__ bias,
                                   float* __restrict__ out) {
    int row = blockIdx.x;
    __shared__ float xs[DD];
    __shared__ float rs[256], rq[256];
    float sum = 0.f, sq = 0.f;
    for (int d = threadIdx.x; d < DD; d += 256) {
        float x = a[(size_t)row*DD + d] + bres[(size_t)row*DD + d];
        xs[d] = x; sum += x; sq += x*x;
    }
    rs[threadIdx.x] = sum; rq[threadIdx.x] = sq;
    __syncthreads();
    for (int s = 128; s > 0; s >>= 1) {
        if (threadIdx.x < s) { rs[threadIdx.x]+=rs[threadIdx.x+s]; rq[threadIdx.x]+=rq[threadIdx.x+s]; }
        __syncthreads();
    }
    float mu = rs[0] * (1.f/DD);
    float var = rq[0] * (1.f/DD) - mu*mu;
    float rstd = rsqrtf(var + 1e-12f);
    for (int d = threadIdx.x; d < DD; d += 256)
        out[(size_t)row*DD + d] = (xs[d]-mu)*rstd*w[d] + bias[d];
}

// ---------------- dense NT SGEMM: C = A(MxK) @ B(NxK)^T [+bias][+gelu] ----------------
// 128x128 tile, BK=8, 256 threads, 8x8 per-thread. M%128==0, N%128==0, K%8==0.
__global__ void __launch_bounds__(256) sgemm_nt_kernel(
        const float* __restrict__ A, const float* __restrict__ B,
        const float* __restrict__ bias, float* __restrict__ C,
        int M, int N, int K, int act) {
    __shared__ float As[8][128];
    __shared__ float Bs[8][128];
    int tid = threadIdx.x;
    int m0 = blockIdx.y * 128;
    int n0 = blockIdx.x * 128;
    int lr = tid >> 1;
    int lc = (tid & 1) * 4;
    const float* Ab = A + (size_t)(m0 + lr) * K + lc;
    const float* Bb = B + (size_t)(n0 + lr) * K + lc;
    int ty = tid >> 4, tx = tid & 15;
    float acc[8][8];
#pragma unroll
    for (int i = 0; i < 8; i++)
#pragma unroll
        for (int j = 0; j < 8; j++) acc[i][j] = 0.f;

    for (int k0 = 0; k0 < K; k0 += 8) {
        float4 a4 = *(const float4*)(Ab + k0);
        float4 b4 = *(const float4*)(Bb + k0);
        As[lc+0][lr] = a4.x; As[lc+1][lr] = a4.y; As[lc+2][lr] = a4.z; As[lc+3][lr] = a4.w;
        Bs[lc+0][lr] = b4.x; Bs[lc+1][lr] = b4.y; Bs[lc+2][lr] = b4.z; Bs[lc+3][lr] = b4.w;
        __syncthreads();
#pragma unroll
        for (int kk = 0; kk < 8; kk++) {
            float4 a0 = *(const float4*)&As[kk][ty*8];
            float4 a1 = *(const float4*)&As[kk][ty*8+4];
            float4 b0 = *(const float4*)&Bs[kk][tx*8];
            float4 b1 = *(const float4*)&Bs[kk][tx*8+4];
            float ra[8] = {a0.x,a0.y,a0.z,a0.w,a1.x,a1.y,a1.z,a1.w};
            float rb[8] = {b0.x,b0.y,b0.z,b0.w,b1.x,b1.y,b1.z,b1.w};
#pragma unroll
            for (int i = 0; i < 8; i++)
#pragma unroll
                for (int j = 0; j < 8; j++)
                    acc[i][j] = fmaf(ra[i], rb[j], acc[i][j]);
        }
        __syncthreads();
    }
#pragma unroll
    for (int i = 0; i < 8; i++) {
        int row = m0 + ty*8 + i;
#pragma unroll
        for (int j = 0; j < 8; j++) {
            int col = n0 + tx*8 + j;
            float c = acc[i][j];
            if (bias) c += bias[col];
            if (act) c = 0.5f * c * (1.f + erff(c * 0.70710678118654752f));
            C[(size_t)row * N + col] = c;
        }
    }
}

// ---------------- attention scores: scores[z,i,j] = (q_i . k_j) * 0.125 ----------------
__global__ void __launch_bounds__(256) scores_kernel() {
    int z = blockIdx.z; int b = z / HH; int h = z % HH;
    const float* qb = g_q + (size_t)b*TT*DD + h*DHH;
    const float* kb = g_k + (size_t)b*TT*DD + h*DHH;
    int i0 = blockIdx.y * 64, j0 = blockIdx.x * 64;
    __shared__ float Qs[64][65];
    __shared__ float Ks[64][65];
    int tid = threadIdx.x;
#pragma unroll
    for (int pp = 0; pp < 16; pp++) {
        int idx = pp*256 + tid;
        int d = idx & 63; int r = idx >> 6;
        Qs[d][r] = qb[(size_t)(i0+r)*DD + d];
        Ks[d][r] = kb[(size_t)(j0+r)*DD + d];
    }
    __syncthreads();
    int ty = tid >> 4, tx = tid & 15;
    float acc[4][4] = {};
#pragma unroll
    for (int d = 0; d < 64; d++) {
        float ra[4], rb[4];
#pragma unroll
        for (int m = 0; m < 4; m++) ra[m] = Qs[d][ty*4+m];
#pragma unroll
        for (int n = 0; n < 4; n++) rb[n] = Ks[d][tx*4+n];
#pragma unroll
        for (int m = 0; m < 4; m++)
#pragma unroll
            for (int n = 0; n < 4; n++)
                acc[m][n] = fmaf(ra[m], rb[n], acc[m][n]);
    }
    float* out = g_scores + (size_t)z*TT*TT;
#pragma unroll
    for (int m = 0; m < 4; m++)
#pragma unroll
        for (int n = 0; n < 4; n++)
            out[(size_t)(i0+ty*4+m)*TT + j0+tx*4+n] = acc[m][n] * 0.125f;
}

// ---------------- bias + mask + softmax (in place over g_scores rows) ----------------
__global__ void __launch_bounds__(128) softmax_kernel(const float* __restrict__ compat_l,
                                                      const float* __restrict__ gamma_l,
                                                      const int* __restrict__ mask) {
    int idx = blockIdx.x;         // z*T + i
    int z = idx / TT; int i = idx % TT;
    int b = z / HH; int h = z % HH;
    float* row = g_scores + (size_t)idx * TT;
    float pi0 = g_p[(b*TT+i)*2], pi1 = g_p[(b*TT+i)*2+1];
    const float* C = compat_l + h*4;
    float cp0 = pi0*C[0] + pi1*C[2];
    float cp1 = pi0*C[1] + pi1*C[3];
    float gm = gamma_l[0];
    int tid = threadIdx.x;
    float vals[4];
    float mx = -1e30f;
#pragma unroll
    for (int jj = 0; jj < 4; jj++) {
        int j = jj*128 + tid;
        int gj = b*TT + j;
        float v = row[j] + cp0*g_p[gj*2] + cp1*g_p[gj*2+1] + gm*g_s[gj]
                  + (1.f - (float)mask[gj]) * -10000.f;
        vals[jj] = v;
        mx = fmaxf(mx, v);
    }
    __shared__ float smax[4], ssum[4];
#pragma unroll
    for (int o = 16; o > 0; o >>= 1) mx = fmaxf(mx, __shfl_xor_sync(0xffffffffu, mx, o));
    if ((tid & 31) == 0) smax[tid >> 5] = mx;
    __syncthreads();
    mx = fmaxf(fmaxf(smax[0], smax[1]), fmaxf(smax[2], smax[3]));
    float sum = 0.f;
#pragma unroll
    for (int jj = 0; jj < 4; jj++) { vals[jj] = expf(vals[jj] - mx); sum += vals[jj]; }
#pragma unroll
    for (int o = 16; o > 0; o >>= 1) sum += __shfl_xor_sync(0xffffffffu, sum, o);
    if ((tid & 31) == 0) ssum[tid >> 5] = sum;
    __syncthreads();
    float inv = 1.f / (ssum[0] + ssum[1] + ssum[2] + ssum[3]);
#pragma unroll
    for (int jj = 0; jj < 4; jj++)
        row[jj*128 + tid] = vals[jj] * inv;
}

// ---------------- ctx = attn @ v, merged-head output (B,T,D) ----------------
__global__ void __launch_bounds__(256) ctx_kernel() {
    int z = blockIdx.y; int b = z / HH; int h = z % HH;
    int i0 = blockIdx.x * 64;
    const float* attn = g_scores + (size_t)z*TT*TT;
    const float* vb = g_v + (size_t)b*TT*DD + h*DHH;
    __shared__ float As[16][65];
    __shared__ float Vs[16][65];
    int tid = threadIdx.x;
    int ty = tid >> 4, tx = tid & 15;
    int aii = tid >> 2; int akc = (tid & 3) * 4;
    float acc[4][4] = {};
    for (int k0 = 0; k0 < TT; k0 += 16) {
        float4 a4 = *(const float4*)(attn + (size_t)(i0+aii)*TT + k0 + akc);
        As[akc+0][aii] = a4.x; As[akc+1][aii] = a4.y; As[akc+2][aii] = a4.z; As[akc+3][aii] = a4.w;
#pragma unroll
        for (int pq = 0; pq < 4; pq++) {
            int kk = (tid >> 6) + pq*4;
            int n = tid & 63;
            Vs[kk][n] = vb[(size_t)(k0+kk)*DD + n];
        }
        __syncthreads();
#pragma unroll
        for (int kk = 0; kk < 16; kk++) {
            float ra[4], rb[4];
#pragma unroll
            for (int m = 0; m < 4; m++) ra[m] = As[kk][ty*4+m];
#pragma unroll
            for (int n = 0; n < 4; n++) rb[n] = Vs[kk][tx*4+n];
#pragma unroll
            for (int m = 0; m < 4; m++)
#pragma unroll
                for (int n = 0; n < 4; n++)
                    acc[m][n] = fmaf(ra[m], rb[n], acc[m][n]);
        }
        __syncthreads();
    }
#pragma unroll
    for (int m = 0; m < 4; m++)
#pragma unroll
        for (int n = 0; n < 4; n++)
            g_ctx[(size_t)(b*TT + i0 + ty*4 + m)*DD + h*DHH + tx*4 + n] = acc[m][n];
}

// ---------------- host launch ----------------
extern "C" void kernel_launch(void* const* d_in, const int* in_sizes, int n_in,
                              void* d_out, int out_size) {
    const int*   ids      = (const int*)  d_in[0];
    const int*   mask     = (const int*)  d_in[1];
    const float* tok      = (const float*)d_in[2];
    const float* pos      = (const float*)d_in[3];
    const float* lang     = (const float*)d_in[4];
    const float* sw       = (const float*)d_in[5];
    const float* proto    = (const float*)d_in[6];
    const float* log_tau  = (const float*)d_in[7];
    const float* eln_w    = (const float*)d_in[8];
    const float* eln_b    = (const float*)d_in[9];
    const float* Wq       = (const float*)d_in[10];
    const float* Wk       = (const float*)d_in[11];
    const float* Wv       = (const float*)d_in[12];
    const float* Wo       = (const float*)d_in[13];
    const float* Wob      = (const float*)d_in[14];
    const float* compat   = (const float*)d_in[15];
    const float* gamma    = (const float*)d_in[16];
    const float* W1       = (const float*)d_in[17];
    const float* b1       = (const float*)d_in[18];
    const float* W2       = (const float*)d_in[19];
    const float* b2       = (const float*)d_in[20];
    const float* ln1w     = (const float*)d_in[21];
    const float* ln1b     = (const float*)d_in[22];
    const float* ln2w     = (const float*)d_in[23];
    const float* ln2b     = (const float*)d_in[24];
    float* out = (float*)d_out;

    float *h, *q, *k, *v, *ctx, *attnout, *hmid, *ffn1, *ffn2;
    cudaGetSymbolAddress((void**)&h,       g_h);
    cudaGetSymbolAddress((void**)&q,       g_q);
    cudaGetSymbolAddress((void**)&k,       g_k);
    cudaGetSymbolAddress((void**)&v,       g_v);
    cudaGetSymbolAddress((void**)&ctx,     g_ctx);
    cudaGetSymbolAddress((void**)&attnout, g_attnout);
    cudaGetSymbolAddress((void**)&hmid,    g_hmid);
    cudaGetSymbolAddress((void**)&ffn1,    g_ffn1);
    cudaGetSymbolAddress((void**)&ffn2,    g_ffn2);

    embed_base_kernel<<<BT, 256>>>(ids, tok, pos, proto, log_tau);
    switch_kernel<<<(BT + 255)/256, 256>>>();
    embed_ln_kernel<<<BT, 256>>>(lang, sw, eln_w, eln_b);

    for (int l = 0; l < LL; l++) {
        const size_t wdd = (size_t)l * DD * DD;
        sgemm_nt_kernel<<<dim3(DD/128, BT/128), 256>>>(h, Wq + wdd, nullptr, q, BT, DD, DD, 0);
        sgemm_nt_kernel<<<dim3(DD/128, BT/128), 256>>>(h, Wk + wdd, nullptr, k, BT, DD, DD, 0);
        sgemm_nt_kernel<<<dim3(DD/128, BT/128), 256>>>(h, Wv + wdd, nullptr, v, BT, DD, DD, 0);

        scores_kernel<<<dim3(TT/64, TT/64, ZZ), 256>>>();
        softmax_kernel<<<ZZ*TT, 128>>>(compat + (size_t)l*HH*4, gamma + l, mask);
        ctx_kernel<<<dim3(TT/64, ZZ), 256>>>();

        sgemm_nt_kernel<<<dim3(DD/128, BT/128), 256>>>(ctx, Wo + wdd, Wob + (size_t)l*DD, attnout, BT, DD, DD, 0);
        ln_residual_kernel<<<BT, 256>>>(h, attnout, ln1w + (size_t)l*DD, ln1b + (size_t)l*DD, hmid);

        sgemm_nt_kernel<<<dim3(FF/128, BT/128), 256>>>(hmid, W1 + (size_t)l*FF*DD, b1 + (size_t)l*FF, ffn1, BT, FF, DD, 1);
        sgemm_nt_kernel<<<dim3(DD/128, BT/128), 256>>>(ffn1, W2 + (size_t)l*DD*FF, b2 + (size_t)l*DD, ffn2, BT, DD, FF, 0);

        float* hout = (l == LL-1) ? out : h;
        ln_residual_kernel<<<BT, 256>>>(hmid, ffn2, ln2w + (size_t)l*DD, ln2b + (size_t)l*DD, hout);
    }
}

// round 3
// speedup vs baseline: 2.8521x; 2.8521x over previous
#include <cuda_runtime.h>
#include <math.h>

#define BB 8
#define TT 512
#define DD 768
#define HH 12
#define DHH 64
#define FF 3072
#define LL 12
#define BT (BB*TT)      // 4096
#define ZZ (BB*HH)      // 96

// ---------------- scratch (device globals; no allocation) ----------------
__device__ float g_hbase[BT*DD];
__device__ float g_p[BT*2];
__device__ float g_s[BT];
__device__ float g_h[BT*DD];
__device__ float g_q[BT*DD];
__device__ float g_k[BT*DD];
__device__ float g_v[BT*DD];
__device__ float g_scores[(size_t)ZZ*TT*TT];
__device__ float g_ctx[BT*DD];
__device__ float g_attnout[BT*DD];
__device__ float g_hmid[BT*DD];
__device__ float g_ffn1[(size_t)BT*FF];
__device__ float g_ffn2[BT*DD];

__device__ __forceinline__ float f2tf(float x) {
    unsigned r;
    asm("cvt.rna.tf32.f32 %0, %1;" : "=r"(r) : "f"(x));
    return __uint_as_float(r);
}

// =============== tf32 tensor-core GEMM ===============
// C[M,N] = A[M,K] @ op(B),  A row-major (lda), C row-major (ldc).
// BNT=true:  B stored [N,K] row-major (ldb) -> C = A @ B^T  (weights, scores)
// BNT=false: B stored [K,N] row-major (ldb) -> C = A @ B    (ctx = attn @ v)
// Batched via blockIdx.z with (batch, head) decomposition.
template<int BM, int BN, int WARPS_M, int WARPS_N, bool BNT>
__global__ __launch_bounds__(WARPS_M*WARPS_N*32, 2)
void mma_gemm(const float* __restrict__ Ag, const float* __restrict__ Bg,
              const float* __restrict__ bias, float* __restrict__ Cg,
              int K, int lda, int ldb, int ldc, int nheads,
              long sAb, long sAh, long sBb, long sBh, long sCb, long sCh,
              float scale, int act)
{
    constexpr int BK = 16;
    constexpr int NTHR = WARPS_M*WARPS_N*32;
    constexpr int WM = BM/WARPS_M, WN = BN/WARPS_N;
    constexpr int MI = WM/16, NI = WN/8;
    constexpr int AP = 20;                      // [BM][20] k-minor, stride 20 (cf-free reads)
    constexpr int BS0 = BNT ? BN : BK;
    constexpr int BS1 = BNT ? 20 : (BN + 8);    // NN: [BK][BN+8], stride%32==8 (cf-free reads)

    __shared__ float As[2][BM][AP];
    __shared__ float Bs[2][BS0][BS1];

    const int z  = blockIdx.z;
    const int bb = z / nheads, hh = z % nheads;
    const float* A = Ag + (long)bb*sAb + (long)hh*sAh;
    const float* B = Bg + (long)bb*sBb + (long)hh*sBh;
    float*       C = Cg + (long)bb*sCb + (long)hh*sCh;

    const int m0 = blockIdx.y * BM;
    const int n0 = blockIdx.x * BN;
    const int tid = threadIdx.x;
    const int warp = tid >> 5, lane = tid & 31;
    const int wm = warp % WARPS_M, wn = warp / WARPS_M;
    const int g = lane >> 2, tig = lane & 3;

    // --- staging loaders ---
    constexpr int AROWS = NTHR/4;               // rows per pass (64)
    constexpr int A_IT = BM/AROWS;
    const int ar = tid >> 2;
    const int ak = (tid & 3) * 4;
    float4 pa[A_IT];

    constexpr int B_IT_NT = BN/AROWS;
    constexpr int BCOLS = BN/4;                 // NN: threads per k-row
    constexpr int BKR = NTHR/BCOLS;             // NN: k-rows per pass
    constexpr int B_IT_NN = BK/BKR;
    constexpr int B_IT = BNT ? B_IT_NT : B_IT_NN;
    const int bkr = tid / BCOLS;
    const int bnc = (tid % BCOLS) * 4;
    float4 pb[B_IT];

    auto fetchA = [&](int k0) {
#pragma unroll
        for (int i = 0; i < A_IT; i++)
            pa[i] = *(const float4*)(A + (size_t)(m0 + ar + i*AROWS)*lda + k0 + ak);
    };
    auto fetchB = [&](int k0) {
        if constexpr (BNT) {
#pragma unroll
            for (int i = 0; i < B_IT; i++)
                pb[i] = *(const float4*)(B + (size_t)(n0 + ar + i*AROWS)*ldb + k0 + ak);
        } else {
#pragma unroll
            for (int i = 0; i < B_IT; i++)
                pb[i] = *(const float4*)(B + (size_t)(k0 + bkr + i*BKR)*ldb + n0 + bnc);
        }
    };
    auto stage = [&](int buf) {
#pragma unroll
        for (int i = 0; i < A_IT; i++) {
            float* d = &As[buf][ar + i*AROWS][ak];
            d[0] = f2tf(pa[i].x); d[1] = f2tf(pa[i].y);
            d[2] = f2tf(pa[i].z); d[3] = f2tf(pa[i].w);
        }
        if constexpr (BNT) {
#pragma unroll
            for (int i = 0; i < B_IT; i++) {
                float* d = &Bs[buf][ar + i*AROWS][ak];
                d[0] = f2tf(pb[i].x); d[1] = f2tf(pb[i].y);
                d[2] = f2tf(pb[i].z); d[3] = f2tf(pb[i].w);
            }
        } else {
#pragma unroll
            for (int i = 0; i < B_IT; i++) {
                float* d = &Bs[buf][bkr + i*BKR][bnc];
                d[0] = f2tf(pb[i].x); d[1] = f2tf(pb[i].y);
                d[2] = f2tf(pb[i].z); d[3] = f2tf(pb[i].w);
            }
        }
    };

    float acc[MI][NI][4];
#pragma unroll
    for (int mi = 0; mi < MI; mi++)
#pragma unroll
        for (int ni = 0; ni < NI; ni++)
#pragma unroll
            for (int r = 0; r < 4; r++) acc[mi][ni][r] = 0.f;

    auto compute = [&](int buf) {
#pragma unroll
        for (int kk = 0; kk < BK; kk += 8) {
            unsigned af[MI][4];
#pragma unroll
            for (int mi = 0; mi < MI; mi++) {
                int am = wm*WM + mi*16;
                af[mi][0] = __float_as_uint(As[buf][am + g    ][kk + tig    ]);
                af[mi][1] = __float_as_uint(As[buf][am + g + 8][kk + tig    ]);
                af[mi][2] = __float_as_uint(As[buf][am + g    ][kk + tig + 4]);
                af[mi][3] = __float_as_uint(As[buf][am + g + 8][kk + tig + 4]);
            }
            unsigned bf[NI][2];
#pragma unroll
            for (int ni = 0; ni < NI; ni++) {
                int bn = wn*WN + ni*8;
                if constexpr (BNT) {
                    bf[ni][0] = __float_as_uint(Bs[buf][bn + g][kk + tig    ]);
                    bf[ni][1] = __float_as_uint(Bs[buf][bn + g][kk + tig + 4]);
                } else {
                    bf[ni][0] = __float_as_uint(Bs[buf][kk + tig    ][bn + g]);
                    bf[ni][1] = __float_as_uint(Bs[buf][kk + tig + 4][bn + g]);
                }
            }
#pragma unroll
            for (int mi = 0; mi < MI; mi++)
#pragma unroll
                for (int ni = 0; ni < NI; ni++)
                    asm volatile(
                        "mma.sync.aligned.m16n8k8.row.col.f32.tf32.tf32.f32 "
                        "{%0,%1,%2,%3},{%4,%5,%6,%7},{%8,%9},{%0,%1,%2,%3};"
                        : "+f"(acc[mi][ni][0]), "+f"(acc[mi][ni][1]),
                          "+f"(acc[mi][ni][2]), "+f"(acc[mi][ni][3])
                        : "r"(af[mi][0]), "r"(af[mi][1]), "r"(af[mi][2]), "r"(af[mi][3]),
                          "r"(bf[ni][0]), "r"(bf[ni][1]));
        }
    };

    fetchA(0); fetchB(0);
    stage(0);
    __syncthreads();
    int buf = 0;
    const int nk = K / BK;
    for (int it = 1; it < nk; it++) {
        fetchA(it*BK); fetchB(it*BK);
        compute(buf);
        stage(buf ^ 1);
        __syncthreads();
        buf ^= 1;
    }
    compute(buf);

    // --- epilogue ---
#pragma unroll
    for (int mi = 0; mi < MI; mi++) {
        int row0 = m0 + wm*WM + mi*16 + g;
#pragma unroll
        for (int ni = 0; ni < NI; ni++) {
            int col = n0 + wn*WN + ni*8 + tig*2;
            float c0 = acc[mi][ni][0]*scale, c1 = acc[mi][ni][1]*scale;
            float c2 = acc[mi][ni][2]*scale, c3 = acc[mi][ni][3]*scale;
            if (bias) {
                float b0 = bias[col], b1 = bias[col+1];
                c0 += b0; c1 += b1; c2 += b0; c3 += b1;
            }
            if (act) {
                c0 = 0.5f*c0*(1.f + erff(c0*0.70710678118654752f));
                c1 = 0.5f*c1*(1.f + erff(c1*0.70710678118654752f));
                c2 = 0.5f*c2*(1.f + erff(c2*0.70710678118654752f));
                c3 = 0.5f*c3*(1.f + erff(c3*0.70710678118654752f));
            }
            *(float2*)&C[(size_t)row0*ldc + col]      = make_float2(c0, c1);
            *(float2*)&C[(size_t)(row0+8)*ldc + col]  = make_float2(c2, c3);
        }
    }
}

// ---------------- stage 1: h_base + language distribution p ----------------
__global__ void embed_base_kernel(const int* __restrict__ ids,
                                  const float* __restrict__ tok,
                                  const float* __restrict__ pos,
                                  const float* __restrict__ proto,
                                  const float* __restrict__ log_tau) {
    int row = blockIdx.x;
    int t = row % TT;
    int id = ids[row];
    const float* trow = tok + (size_t)id * DD;
    const float* prow = pos + (size_t)t * DD;
    float a0 = 0.f, a1 = 0.f;
    __shared__ float r0[256], r1[256];
    for (int d = threadIdx.x; d < DD; d += 256) {
        float v = trow[d] + prow[d];
        g_hbase[(size_t)row*DD + d] = v;
        a0 += v * proto[d];
        a1 += v * proto[DD + d];
    }
    r0[threadIdx.x] = a0; r1[threadIdx.x] = a1;
    __syncthreads();
    for (int s = 128; s > 0; s >>= 1) {
        if (threadIdx.x < s) {
            r0[threadIdx.x] += r0[threadIdx.x + s];
            r1[threadIdx.x] += r1[threadIdx.x + s];
        }
        __syncthreads();
    }
    if (threadIdx.x == 0) {
        float tau = fmaxf(expf(log_tau[0]), 0.25f);
        float l0 = r0[0] / tau, l1 = r1[0] / tau;
        float m = fmaxf(l0, l1);
        float e0 = expf(l0 - m), e1 = expf(l1 - m);
        float inv = 1.f / (e0 + e1);
        g_p[row*2 + 0] = e0 * inv;
        g_p[row*2 + 1] = e1 * inv;
    }
}

__global__ void switch_kernel() {
    int i = blockIdx.x * blockDim.x + threadIdx.x;
    if (i >= BT) return;
    int t = i % TT;
    float sv = 0.f;
    if (t > 0)
        sv = 1.f - (g_p[i*2]*g_p[(i-1)*2] + g_p[i*2+1]*g_p[(i-1)*2+1]);
    g_s[i] = sv;
}

__global__ void embed_ln_kernel(const float* __restrict__ lang,
                                const float* __restrict__ sw,
                                const float* __restrict__ w,
                                const float* __restrict__ b) {
    int row = blockIdx.x;
    __shared__ float xs[DD];
    __shared__ float rs[256], rq[256];
    float p0 = g_p[row*2], p1 = g_p[row*2+1], sv = g_s[row];
    float sum = 0.f, sq = 0.f;
    for (int d = threadIdx.x; d < DD; d += 256) {
        float x = g_hbase[(size_t)row*DD + d] + p0*lang[d] + p1*lang[DD+d] + sv*sw[d];
        xs[d] = x; sum += x; sq += x*x;
    }
    rs[threadIdx.x] = sum; rq[threadIdx.x] = sq;
    __syncthreads();
    for (int s = 128; s > 0; s >>= 1) {
        if (threadIdx.x < s) { rs[threadIdx.x]+=rs[threadIdx.x+s]; rq[threadIdx.x]+=rq[threadIdx.x+s]; }
        __syncthreads();
    }
    float mu = rs[0] * (1.f/DD);
    float var = rq[0] * (1.f/DD) - mu*mu;
    float rstd = rsqrtf(var + 1e-12f);
    for (int d = threadIdx.x; d < DD; d += 256)
        g_h[(size_t)row*DD + d] = (xs[d]-mu)*rstd*w[d] + b[d];
}

__global__ void ln_residual_kernel(const float* __restrict__ a,
                                   const float* __restrict__ bres,
                                   const float* __restrict__ w,
                                   const float* __restrict__ bias,
                                   float* __restrict__ out) {
    int row = blockIdx.x;
    __shared__ float xs[DD];
    __shared__ float rs[256], rq[256];
    float sum = 0.f, sq = 0.f;
    for (int d = threadIdx.x; d < DD; d += 256) {
        float x = a[(size_t)row*DD + d] + bres[(size_t)row*DD + d];
        xs[d] = x; sum += x; sq += x*x;
    }
    rs[threadIdx.x] = sum; rq[threadIdx.x] = sq;
    __syncthreads();
    for (int s = 128; s > 0; s >>= 1) {
        if (threadIdx.x < s) { rs[threadIdx.x]+=rs[threadIdx.x+s]; rq[threadIdx.x]+=rq[threadIdx.x+s]; }
        __syncthreads();
    }
    float mu = rs[0] * (1.f/DD);
    float var = rq[0] * (1.f/DD) - mu*mu;
    float rstd = rsqrtf(var + 1e-12f);
    for (int d = threadIdx.x; d < DD; d += 256)
        out[(size_t)row*DD + d] = (xs[d]-mu)*rstd*w[d] + bias[d];
}

// ---------------- bias + mask + softmax (in place over g_scores rows) ----------------
__global__ void __launch_bounds__(128) softmax_kernel(const float* __restrict__ compat_l,
                                                      const float* __restrict__ gamma_l,
                                                      const int* __restrict__ mask) {
    int idx = blockIdx.x;         // z*T + i
    int z = idx / TT; int i = idx % TT;
    int b = z / HH; int h = z % HH;
    float* row = g_scores + (size_t)idx * TT;
    float pi0 = g_p[(b*TT+i)*2], pi1 = g_p[(b*TT+i)*2+1];
    const float* C = compat_l + h*4;
    float cp0 = pi0*C[0] + pi1*C[2];
    float cp1 = pi0*C[1] + pi1*C[3];
    float gm = gamma_l[0];
    int tid = threadIdx.x;
    float vals[4];
    float mx = -1e30f;
#pragma unroll
    for (int jj = 0; jj < 4; jj++) {
        int j = jj*128 + tid;
        int gj = b*TT + j;
        float v = row[j] + cp0*g_p[gj*2] + cp1*g_p[gj*2+1] + gm*g_s[gj]
                  + (1.f - (float)mask[gj]) * -10000.f;
        vals[jj] = v;
        mx = fmaxf(mx, v);
    }
    __shared__ float smax[4], ssum[4];
#pragma unroll
    for (int o = 16; o > 0; o >>= 1) mx = fmaxf(mx, __shfl_xor_sync(0xffffffffu, mx, o));
    if ((tid & 31) == 0) smax[tid >> 5] = mx;
    __syncthreads();
    mx = fmaxf(fmaxf(smax[0], smax[1]), fmaxf(smax[2], smax[3]));
    float sum = 0.f;
#pragma unroll
    for (int jj = 0; jj < 4; jj++) { vals[jj] = expf(vals[jj] - mx); sum += vals[jj]; }
#pragma unroll
    for (int o = 16; o > 0; o >>= 1) sum += __shfl_xor_sync(0xffffffffu, sum, o);
    if ((tid & 31) == 0) ssum[tid >> 5] = sum;
    __syncthreads();
    float inv = 1.f / (ssum[0] + ssum[1] + ssum[2] + ssum[3]);
#pragma unroll
    for (int jj = 0; jj < 4; jj++)
        row[jj*128 + tid] = vals[jj] * inv;
}

// ---------------- host launch ----------------
extern "C" void kernel_launch(void* const* d_in, const int* in_sizes, int n_in,
                              void* d_out, int out_size) {
    const int*   ids      = (const int*)  d_in[0];
    const int*   mask     = (const int*)  d_in[1];
    const float* tok      = (const float*)d_in[2];
    const float* pos      = (const float*)d_in[3];
    const float* lang     = (const float*)d_in[4];
    const float* sw       = (const float*)d_in[5];
    const float* proto    = (const float*)d_in[6];
    const float* log_tau  = (const float*)d_in[7];
    const float* eln_w    = (const float*)d_in[8];
    const float* eln_b    = (const float*)d_in[9];
    const float* Wq       = (const float*)d_in[10];
    const float* Wk       = (const float*)d_in[11];
    const float* Wv       = (const float*)d_in[12];
    const float* Wo       = (const float*)d_in[13];
    const float* Wob      = (const float*)d_in[14];
    const float* compat   = (const float*)d_in[15];
    const float* gamma    = (const float*)d_in[16];
    const float* W1       = (const float*)d_in[17];
    const float* b1       = (const float*)d_in[18];
    const float* W2       = (const float*)d_in[19];
    const float* b2       = (const float*)d_in[20];
    const float* ln1w     = (const float*)d_in[21];
    const float* ln1b     = (const float*)d_in[22];
    const float* ln2w     = (const float*)d_in[23];
    const float* ln2b     = (const float*)d_in[24];
    float* out = (float*)d_out;

    float *h, *q, *k, *v, *scores, *ctx, *attnout, *hmid, *ffn1, *ffn2;
    cudaGetSymbolAddress((void**)&h,       g_h);
    cudaGetSymbolAddress((void**)&q,       g_q);
    cudaGetSymbolAddress((void**)&k,       g_k);
    cudaGetSymbolAddress((void**)&v,       g_v);
    cudaGetSymbolAddress((void**)&scores,  g_scores);
    cudaGetSymbolAddress((void**)&ctx,     g_ctx);
    cudaGetSymbolAddress((void**)&attnout, g_attnout);
    cudaGetSymbolAddress((void**)&hmid,    g_hmid);
    cudaGetSymbolAddress((void**)&ffn1,    g_ffn1);
    cudaGetSymbolAddress((void**)&ffn2,    g_ffn2);

    embed_base_kernel<<<BT, 256>>>(ids, tok, pos, proto, log_tau);
    switch_kernel<<<(BT + 255)/256, 256>>>();
    embed_ln_kernel<<<BT, 256>>>(lang, sw, eln_w, eln_b);

    const dim3 gDense(DD/128, BT/128, 1);       // 6 x 32
    const dim3 gFfn1(FF/128, BT/128, 1);        // 24 x 32
    const dim3 gScores(TT/128, TT/128, ZZ);     // 4 x 4 x 96
    const dim3 gCtx(DHH/64, TT/128, ZZ);        // 1 x 4 x 96

    for (int l = 0; l < LL; l++) {
        const size_t wdd = (size_t)l * DD * DD;
        // QKV
        mma_gemm<128,128,2,4,true><<<gDense, 256>>>(h, Wq + wdd, nullptr, q,
            DD, DD, DD, DD, 1, 0,0,0,0,0,0, 1.f, 0);
        mma_gemm<128,128,2,4,true><<<gDense, 256>>>(h, Wk + wdd, nullptr, k,
            DD, DD, DD, DD, 1, 0,0,0,0,0,0, 1.f, 0);
        mma_gemm<128,128,2,4,true><<<gDense, 256>>>(h, Wv + wdd, nullptr, v,
            DD, DD, DD, DD, 1, 0,0,0,0,0,0, 1.f, 0);

        // scores[z] = (q_bh @ k_bh^T) * 0.125
        mma_gemm<128,128,2,4,true><<<gScores, 256>>>(q, k, nullptr, scores,
            DHH, DD, DD, TT, HH,
            (long)TT*DD, DHH, (long)TT*DD, DHH,
            (long)HH*TT*TT, (long)TT*TT, 0.125f, 0);

        softmax_kernel<<<ZZ*TT, 128>>>(compat + (size_t)l*HH*4, gamma + l, mask);

        // ctx[z] = attn[z] @ v_bh   (B is K x N row-major)
        mma_gemm<128,64,4,2,false><<<gCtx, 256>>>(scores, v, nullptr, ctx,
            TT, TT, DD, DD, HH,
            (long)HH*TT*TT, (long)TT*TT, (long)TT*DD, DHH,
            (long)TT*DD, DHH, 1.f, 0);

        // Wo
        mma_gemm<128,128,2,4,true><<<gDense, 256>>>(ctx, Wo + wdd, Wob + (size_t)l*DD, attnout,
            DD, DD, DD, DD, 1, 0,0,0,0,0,0, 1.f, 0);
        ln_residual_kernel<<<BT, 256>>>(h, attnout, ln1w + (size_t)l*DD, ln1b + (size_t)l*DD, hmid);

        // FFN
        mma_gemm<128,128,2,4,true><<<gFfn1, 256>>>(hmid, W1 + (size_t)l*FF*DD, b1 + (size_t)l*FF, ffn1,
            DD, DD, DD, FF, 1, 0,0,0,0,0,0, 1.f, 1);
        mma_gemm<128,128,2,4,true><<<gDense, 256>>>(ffn1, W2 + (size_t)l*DD*FF, b2 + (size_t)l*DD, ffn2,
            FF, FF, FF, DD, 1, 0,0,0,0,0,0, 1.f, 0);

        float* hout = (l == LL-1) ? out : h;
        ln_residual_kernel<<<BT, 256>>>(hmid, ffn2, ln2w + (size_t)l*DD, ln2b + (size_t)l*DD, hout);
    }
}

// round 5
// speedup vs baseline: 3.0095x; 1.0552x over previous
#include <cuda_runtime.h>
#include <math.h>

#define BB 8
#define TT 512
#define DD 768
#define HH 12
#define DHH 64
#define FF 3072
#define LL 12
#define BT (BB*TT)      // 4096
#define ZZ (BB*HH)      // 96

// ---------------- scratch (device globals; no allocation) ----------------
__device__ float g_hbase[BT*DD];
__device__ float g_p[BT*2];
__device__ float g_s[BT];
__device__ float g_h[BT*DD];
__device__ float g_q[BT*DD];
__device__ float g_k[BT*DD];
__device__ float g_v[BT*DD];
__device__ float g_scores[(size_t)ZZ*TT*TT];
__device__ float g_ctx[BT*DD];
__device__ float g_attnout[BT*DD];
__device__ float g_hmid[BT*DD];
__device__ float g_ffn1[(size_t)BT*FF];
__device__ float g_ffn2[BT*DD];

__device__ __forceinline__ float f2tf(float x) {
    unsigned r;
    asm("cvt.rna.tf32.f32 %0, %1;" : "=r"(r) : "f"(x));
    return __uint_as_float(r);
}

// =============== tf32 tensor-core GEMM (round-3 core: register-staged double buffer) ===============
// C[M,N] = A[M,K] @ op(B),  A row-major (lda), C row-major (ldc).
// BNT=true:  B stored [N,K] row-major -> C = A @ B^T  (weights, scores)
// BNT=false: B stored [K,N] row-major -> C = A @ B    (ctx = attn @ v)
// FUSE3: blockIdx.z in {0,1,2} selects (Bg,Cg)/(B1g,C1g)/(B2g,C2g) [QKV]
template<int BM, int BN, int WARPS_M, int WARPS_N, bool BNT, bool FUSE3>
__global__ __launch_bounds__(WARPS_M*WARPS_N*32, 2)
void mma_gemm(const float* __restrict__ Ag, const float* __restrict__ Bg,
              const float* __restrict__ B1g, const float* __restrict__ B2g,
              const float* __restrict__ bias, float* __restrict__ Cg,
              float* __restrict__ C1g, float* __restrict__ C2g,
              int K, int lda, int ldb, int ldc, int nheads,
              long sAb, long sAh, long sBb, long sBh, long sCb, long sCh,
              float scale, int act)
{
    constexpr int BK = 16;
    constexpr int NTHR = WARPS_M*WARPS_N*32;
    constexpr int WM = BM/WARPS_M, WN = BN/WARPS_N;
    constexpr int MI = WM/16, NI = WN/8;
    constexpr int AP = 20;                      // stride 20: conflict-free frag reads
    constexpr int BS0 = BNT ? BN : BK;
    constexpr int BS1 = BNT ? 20 : (BN + 8);    // NN stride%32==8: conflict-free

    __shared__ float As[2][BM][AP];
    __shared__ float Bs[2][BS0][BS1];

    const int z  = blockIdx.z;
    const int bb = z / nheads, hh = z % nheads;
    const float* A = Ag + (long)bb*sAb + (long)hh*sAh;
    const float* B;
    float*       C;
    if constexpr (FUSE3) {
        B = (z == 0) ? Bg : (z == 1) ? B1g : B2g;
        C = (z == 0) ? Cg : (z == 1) ? C1g : C2g;
    } else {
        B = Bg + (long)bb*sBb + (long)hh*sBh;
        C = Cg + (long)bb*sCb + (long)hh*sCh;
    }

    const int m0 = blockIdx.y * BM;
    const int n0 = blockIdx.x * BN;
    const int tid = threadIdx.x;
    const int warp = tid >> 5, lane = tid & 31;
    const int wm = warp % WARPS_M, wn = warp / WARPS_M;
    const int g = lane >> 2, tig = lane & 3;

    // --- staging loaders ---
    constexpr int AROWS = NTHR/4;               // rows per pass (64)
    constexpr int A_IT = BM/AROWS;
    const int ar = tid >> 2;
    const int ak = (tid & 3) * 4;
    float4 pa[A_IT];

    constexpr int B_IT_NT = BN/AROWS;
    constexpr int BCOLS = BN/4;                 // NN: threads per k-row
    constexpr int BKR = NTHR/BCOLS;             // NN: k-rows per pass
    constexpr int B_IT_NN = BK/BKR;
    constexpr int B_IT = BNT ? B_IT_NT : B_IT_NN;
    const int bkr = tid / BCOLS;
    const int bnc = (tid % BCOLS) * 4;
    float4 pb[B_IT];

    auto fetchA = [&](int k0) {
#pragma unroll
        for (int i = 0; i < A_IT; i++)
            pa[i] = *(const float4*)(A + (size_t)(m0 + ar + i*AROWS)*lda + k0 + ak);
    };
    auto fetchB = [&](int k0) {
        if constexpr (BNT) {
#pragma unroll
            for (int i = 0; i < B_IT; i++)
                pb[i] = *(const float4*)(B + (size_t)(n0 + ar + i*AROWS)*ldb + k0 + ak);
        } else {
#pragma unroll
            for (int i = 0; i < B_IT; i++)
                pb[i] = *(const float4*)(B + (size_t)(k0 + bkr + i*BKR)*ldb + n0 + bnc);
        }
    };
    auto stage = [&](int buf) {
#pragma unroll
        for (int i = 0; i < A_IT; i++) {
            float* d = &As[buf][ar + i*AROWS][ak];
            d[0] = f2tf(pa[i].x); d[1] = f2tf(pa[i].y);
            d[2] = f2tf(pa[i].z); d[3] = f2tf(pa[i].w);
        }
        if constexpr (BNT) {
#pragma unroll
            for (int i = 0; i < B_IT; i++) {
                float* d = &Bs[buf][ar + i*AROWS][ak];
                d[0] = f2tf(pb[i].x); d[1] = f2tf(pb[i].y);
                d[2] = f2tf(pb[i].z); d[3] = f2tf(pb[i].w);
            }
        } else {
#pragma unroll
            for (int i = 0; i < B_IT; i++) {
                float* d = &Bs[buf][bkr + i*BKR][bnc];
                d[0] = f2tf(pb[i].x); d[1] = f2tf(pb[i].y);
                d[2] = f2tf(pb[i].z); d[3] = f2tf(pb[i].w);
            }
        }
    };

    float acc[MI][NI][4];
#pragma unroll
    for (int mi = 0; mi < MI; mi++)
#pragma unroll
        for (int ni = 0; ni < NI; ni++)
#pragma unroll
            for (int r = 0; r < 4; r++) acc[mi][ni][r] = 0.f;

    auto compute = [&](int buf) {
#pragma unroll
        for (int kk = 0; kk < BK; kk += 8) {
            unsigned af[MI][4];
#pragma unroll
            for (int mi = 0; mi < MI; mi++) {
                int am = wm*WM + mi*16;
                af[mi][0] = __float_as_uint(As[buf][am + g    ][kk + tig    ]);
                af[mi][1] = __float_as_uint(As[buf][am + g + 8][kk + tig    ]);
                af[mi][2] = __float_as_uint(As[buf][am + g    ][kk + tig + 4]);
                af[mi][3] = __float_as_uint(As[buf][am + g + 8][kk + tig + 4]);
            }
            unsigned bf[NI][2];
#pragma unroll
            for (int ni = 0; ni < NI; ni++) {
                int bn = wn*WN + ni*8;
                if constexpr (BNT) {
                    bf[ni][0] = __float_as_uint(Bs[buf][bn + g][kk + tig    ]);
                    bf[ni][1] = __float_as_uint(Bs[buf][bn + g][kk + tig + 4]);
                } else {
                    bf[ni][0] = __float_as_uint(Bs[buf][kk + tig    ][bn + g]);
                    bf[ni][1] = __float_as_uint(Bs[buf][kk + tig + 4][bn + g]);
                }
            }
#pragma unroll
            for (int mi = 0; mi < MI; mi++)
#pragma unroll
                for (int ni = 0; ni < NI; ni++)
                    asm volatile(
                        "mma.sync.aligned.m16n8k8.row.col.f32.tf32.tf32.f32 "
                        "{%0,%1,%2,%3},{%4,%5,%6,%7},{%8,%9},{%0,%1,%2,%3};"
                        : "+f"(acc[mi][ni][0]), "+f"(acc[mi][ni][1]),
                          "+f"(acc[mi][ni][2]), "+f"(acc[mi][ni][3])
                        : "r"(af[mi][0]), "r"(af[mi][1]), "r"(af[mi][2]), "r"(af[mi][3]),
                          "r"(bf[ni][0]), "r"(bf[ni][1]));
        }
    };

    fetchA(0); fetchB(0);
    stage(0);
    __syncthreads();
    int buf = 0;
    const int nk = K / BK;
    for (int it = 1; it < nk; it++) {
        fetchA(it*BK); fetchB(it*BK);
        compute(buf);
        stage(buf ^ 1);
        __syncthreads();
        buf ^= 1;
    }
    compute(buf);

    // --- epilogue ---
#pragma unroll
    for (int mi = 0; mi < MI; mi++) {
        int row0 = m0 + wm*WM + mi*16 + g;
#pragma unroll
        for (int ni = 0; ni < NI; ni++) {
            int col = n0 + wn*WN + ni*8 + tig*2;
            float c0 = acc[mi][ni][0]*scale, c1 = acc[mi][ni][1]*scale;
            float c2 = acc[mi][ni][2]*scale, c3 = acc[mi][ni][3]*scale;
            if (bias) {
                float b0 = bias[col], b1 = bias[col+1];
                c0 += b0; c1 += b1; c2 += b0; c3 += b1;
            }
            if (act) {
                c0 = 0.5f*c0*(1.f + erff(c0*0.70710678118654752f));
                c1 = 0.5f*c1*(1.f + erff(c1*0.70710678118654752f));
                c2 = 0.5f*c2*(1.f + erff(c2*0.70710678118654752f));
                c3 = 0.5f*c3*(1.f + erff(c3*0.70710678118654752f));
            }
            *(float2*)&C[(size_t)row0*ldc + col]      = make_float2(c0, c1);
            *(float2*)&C[(size_t)(row0+8)*ldc + col]  = make_float2(c2, c3);
        }
    }
}

// ---------------- stage 1: h_base + language distribution p ----------------
__global__ void embed_base_kernel(const int* __restrict__ ids,
                                  const float* __restrict__ tok,
                                  const float* __restrict__ pos,
                                  const float* __restrict__ proto,
                                  const float* __restrict__ log_tau) {
    int row = blockIdx.x;
    int t = row % TT;
    int id = ids[row];
    const float* trow = tok + (size_t)id * DD;
    const float* prow = pos + (size_t)t * DD;
    float a0 = 0.f, a1 = 0.f;
    __shared__ float r0[256], r1[256];
    for (int d = threadIdx.x; d < DD; d += 256) {
        float v = trow[d] + prow[d];
        g_hbase[(size_t)row*DD + d] = v;
        a0 += v * proto[d];
        a1 += v * proto[DD + d];
    }
    r0[threadIdx.x] = a0; r1[threadIdx.x] = a1;
    __syncthreads();
    for (int s = 128; s > 0; s >>= 1) {
        if (threadIdx.x < s) {
            r0[threadIdx.x] += r0[threadIdx.x + s];
            r1[threadIdx.x] += r1[threadIdx.x + s];
        }
        __syncthreads();
    }
    if (threadIdx.x == 0) {
        float tau = fmaxf(expf(log_tau[0]), 0.25f);
        float l0 = r0[0] / tau, l1 = r1[0] / tau;
        float m = fmaxf(l0, l1);
        float e0 = expf(l0 - m), e1 = expf(l1 - m);
        float inv = 1.f / (e0 + e1);
        g_p[row*2 + 0] = e0 * inv;
        g_p[row*2 + 1] = e1 * inv;
    }
}

__global__ void switch_kernel() {
    int i = blockIdx.x * blockDim.x + threadIdx.x;
    if (i >= BT) return;
    int t = i % TT;
    float sv = 0.f;
    if (t > 0)
        sv = 1.f - (g_p[i*2]*g_p[(i-1)*2] + g_p[i*2+1]*g_p[(i-1)*2+1]);
    g_s[i] = sv;
}

__global__ void embed_ln_kernel(const float* __restrict__ lang,
                                const float* __restrict__ sw,
                                const float* __restrict__ w,
                                const float* __restrict__ b) {
    int row = blockIdx.x;
    __shared__ float xs[DD];
    __shared__ float rs[256], rq[256];
    float p0 = g_p[row*2], p1 = g_p[row*2+1], sv = g_s[row];
    float sum = 0.f, sq = 0.f;
    for (int d = threadIdx.x; d < DD; d += 256) {
        float x = g_hbase[(size_t)row*DD + d] + p0*lang[d] + p1*lang[DD+d] + sv*sw[d];
        xs[d] = x; sum += x; sq += x*x;
    }
    rs[threadIdx.x] = sum; rq[threadIdx.x] = sq;
    __syncthreads();
    for (int s = 128; s > 0; s >>= 1) {
        if (threadIdx.x < s) { rs[threadIdx.x]+=rs[threadIdx.x+s]; rq[threadIdx.x]+=rq[threadIdx.x+s]; }
        __syncthreads();
    }
    float mu = rs[0] * (1.f/DD);
    float var = rq[0] * (1.f/DD) - mu*mu;
    float rstd = rsqrtf(var + 1e-12f);
    for (int d = threadIdx.x; d < DD; d += 256)
        g_h[(size_t)row*DD + d] = (xs[d]-mu)*rstd*w[d] + b[d];
}

__global__ void ln_residual_kernel(const float* __restrict__ a,
                                   const float* __restrict__ bres,
                                   const float* __restrict__ w,
                                   const float* __restrict__ bias,
                                   float* __restrict__ out) {
    int row = blockIdx.x;
    __shared__ float xs[DD];
    __shared__ float rs[256], rq[256];
    float sum = 0.f, sq = 0.f;
    for (int d = threadIdx.x; d < DD; d += 256) {
        float x = a[(size_t)row*DD + d] + bres[(size_t)row*DD + d];
        xs[d] = x; sum += x; sq += x*x;
    }
    rs[threadIdx.x] = sum; rq[threadIdx.x] = sq;
    __syncthreads();
    for (int s = 128; s > 0; s >>= 1) {
        if (threadIdx.x < s) { rs[threadIdx.x]+=rs[threadIdx.x+s]; rq[threadIdx.x]+=rq[threadIdx.x+s]; }
        __syncthreads();
    }
    float mu = rs[0] * (1.f/DD);
    float var = rq[0] * (1.f/DD) - mu*mu;
    float rstd = rsqrtf(var + 1e-12f);
    for (int d = threadIdx.x; d < DD; d += 256)
        out[(size_t)row*DD + d] = (xs[d]-mu)*rstd*w[d] + bias[d];
}

// ---------------- bias + mask + softmax (in place over g_scores rows) ----------------
__global__ void __launch_bounds__(128) softmax_kernel(const float* __restrict__ compat_l,
                                                      const float* __restrict__ gamma_l,
                                                      const int* __restrict__ mask) {
    int idx = blockIdx.x;         // z*T + i
    int z = idx / TT; int i = idx % TT;
    int b = z / HH; int h = z % HH;
    float* row = g_scores + (size_t)idx * TT;
    float pi0 = g_p[(b*TT+i)*2], pi1 = g_p[(b*TT+i)*2+1];
    const float* C = compat_l + h*4;
    float cp0 = pi0*C[0] + pi1*C[2];
    float cp1 = pi0*C[1] + pi1*C[3];
    float gm = gamma_l[0];
    int tid = threadIdx.x;
    float vals[4];
    float mx = -1e30f;
#pragma unroll
    for (int jj = 0; jj < 4; jj++) {
        int j = jj*128 + tid;
        int gj = b*TT + j;
        float v = row[j] + cp0*g_p[gj*2] + cp1*g_p[gj*2+1] + gm*g_s[gj]
                  + (1.f - (float)mask[gj]) * -10000.f;
        vals[jj] = v;
        mx = fmaxf(mx, v);
    }
    __shared__ float smax[4], ssum[4];
#pragma unroll
    for (int o = 16; o > 0; o >>= 1) mx = fmaxf(mx, __shfl_xor_sync(0xffffffffu, mx, o));
    if ((tid & 31) == 0) smax[tid >> 5] = mx;
    __syncthreads();
    mx = fmaxf(fmaxf(smax[0], smax[1]), fmaxf(smax[2], smax[3]));
    float sum = 0.f;
#pragma unroll
    for (int jj = 0; jj < 4; jj++) { vals[jj] = expf(vals[jj] - mx); sum += vals[jj]; }
#pragma unroll
    for (int o = 16; o > 0; o >>= 1) sum += __shfl_xor_sync(0xffffffffu, sum, o);
    if ((tid & 31) == 0) ssum[tid >> 5] = sum;
    __syncthreads();
    float inv = 1.f / (ssum[0] + ssum[1] + ssum[2] + ssum[3]);
#pragma unroll
    for (int jj = 0; jj < 4; jj++)
        row[jj*128 + tid] = vals[jj] * inv;
}

// ---------------- host launch ----------------
extern "C" void kernel_launch(void* const* d_in, const int* in_sizes, int n_in,
                              void* d_out, int out_size) {
    const int*   ids      = (const int*)  d_in[0];
    const int*   mask     = (const int*)  d_in[1];
    const float* tok      = (const float*)d_in[2];
    const float* pos      = (const float*)d_in[3];
    const float* lang     = (const float*)d_in[4];
    const float* sw       = (const float*)d_in[5];
    const float* proto    = (const float*)d_in[6];
    const float* log_tau  = (const float*)d_in[7];
    const float* eln_w    = (const float*)d_in[8];
    const float* eln_b    = (const float*)d_in[9];
    const float* Wq       = (const float*)d_in[10];
    const float* Wk       = (const float*)d_in[11];
    const float* Wv       = (const float*)d_in[12];
    const float* Wo       = (const float*)d_in[13];
    const float* Wob      = (const float*)d_in[14];
    const float* compat   = (const float*)d_in[15];
    const float* gamma    = (const float*)d_in[16];
    const float* W1       = (const float*)d_in[17];
    const float* b1       = (const float*)d_in[18];
    const float* W2       = (const float*)d_in[19];
    const float* b2       = (const float*)d_in[20];
    const float* ln1w     = (const float*)d_in[21];
    const float* ln1b     = (const float*)d_in[22];
    const float* ln2w     = (const float*)d_in[23];
    const float* ln2b     = (const float*)d_in[24];
    float* out = (float*)d_out;

    float *h, *q, *k, *v, *scores, *ctx, *attnout, *hmid, *ffn1, *ffn2;
    cudaGetSymbolAddress((void**)&h,       g_h);
    cudaGetSymbolAddress((void**)&q,       g_q);
    cudaGetSymbolAddress((void**)&k,       g_k);
    cudaGetSymbolAddress((void**)&v,       g_v);
    cudaGetSymbolAddress((void**)&scores,  g_scores);
    cudaGetSymbolAddress((void**)&ctx,     g_ctx);
    cudaGetSymbolAddress((void**)&attnout, g_attnout);
    cudaGetSymbolAddress((void**)&hmid,    g_hmid);
    cudaGetSymbolAddress((void**)&ffn1,    g_ffn1);
    cudaGetSymbolAddress((void**)&ffn2,    g_ffn2);

    embed_base_kernel<<<BT, 256>>>(ids, tok, pos, proto, log_tau);
    switch_kernel<<<(BT + 255)/256, 256>>>();
    embed_ln_kernel<<<BT, 256>>>(lang, sw, eln_w, eln_b);

    const dim3 gQKV(DD/128, BT/128, 3);         // 6 x 32 x 3 = 576
    const dim3 gDense64(DD/128, BT/64, 1);      // 6 x 64 = 384
    const dim3 gFfn1(FF/128, BT/128, 1);        // 24 x 32 = 768
    const dim3 gScores(TT/128, TT/128, ZZ);     // 4 x 4 x 96
    const dim3 gCtx(DHH/64, TT/128, ZZ);        // 1 x 4 x 96

    for (int l = 0; l < LL; l++) {
        const size_t wdd = (size_t)l * DD * DD;
        // fused QKV: blockIdx.z selects (Wq->q, Wk->k, Wv->v)
        mma_gemm<128,128,2,4,true,true><<<gQKV, 256>>>(h, Wq + wdd, Wk + wdd, Wv + wdd,
            nullptr, q, k, v,
            DD, DD, DD, DD, 1, 0,0,0,0,0,0, 1.f, 0);

        // scores[z] = (q_bh @ k_bh^T) * 0.125
        mma_gemm<128,128,2,4,true,false><<<gScores, 256>>>(q, k, nullptr, nullptr,
            nullptr, scores, nullptr, nullptr,
            DHH, DD, DD, TT, HH,
            (long)TT*DD, DHH, (long)TT*DD, DHH,
            (long)HH*TT*TT, (long)TT*TT, 0.125f, 0);

        softmax_kernel<<<ZZ*TT, 128>>>(compat + (size_t)l*HH*4, gamma + l, mask);

        // ctx[z] = attn[z] @ v_bh
        mma_gemm<128,64,4,2,false,false><<<gCtx, 256>>>(scores, v, nullptr, nullptr,
            nullptr, ctx, nullptr, nullptr,
            TT, TT, DD, DD, HH,
            (long)HH*TT*TT, (long)TT*TT, (long)TT*DD, DHH,
            (long)TT*DD, DHH, 1.f, 0);

        // Wo (BM=64 tiles: 384 CTAs)
        mma_gemm<64,128,2,4,true,false><<<gDense64, 256>>>(ctx, Wo + wdd, nullptr, nullptr,
            Wob + (size_t)l*DD, attnout, nullptr, nullptr,
            DD, DD, DD, DD, 1, 0,0,0,0,0,0, 1.f, 0);
        ln_residual_kernel<<<BT, 256>>>(h, attnout, ln1w + (size_t)l*DD, ln1b + (size_t)l*DD, hmid);

        // FFN
        mma_gemm<128,128,2,4,true,false><<<gFfn1, 256>>>(hmid, W1 + (size_t)l*FF*DD, nullptr, nullptr,
            b1 + (size_t)l*FF, ffn1, nullptr, nullptr,
            DD, DD, DD, FF, 1, 0,0,0,0,0,0, 1.f, 1);
        mma_gemm<64,128,2,4,true,false><<<gDense64, 256>>>(ffn1, W2 + (size_t)l*DD*FF, nullptr, nullptr,
            b2 + (size_t)l*DD, ffn2, nullptr, nullptr,
            FF, FF, FF, DD, 1, 0,0,0,0,0,0, 1.f, 0);

        float* hout = (l == LL-1) ? out : h;
        ln_residual_kernel<<<BT, 256>>>(hmid, ffn2, ln2w + (size_t)l*DD, ln2b + (size_t)l*DD, hout);
    }
}

// round 6
// speedup vs baseline: 3.4696x; 1.1529x over previous
#include <cuda_runtime.h>
#include <math.h>

#define BB 8
#define TT 512
#define DD 768
#define HH 12
#define DHH 64
#define FF 3072
#define LL 12
#define BT (BB*TT)      // 4096
#define ZZ (BB*HH)      // 96

// ---------------- scratch (device globals; no allocation) ----------------
__device__ float g_hbase[BT*DD];
__device__ float g_p[BT*2];
__device__ float g_s[BT];
__device__ float g_h[BT*DD];
__device__ float g_q[BT*DD];
__device__ float g_k[BT*DD];
__device__ float g_v[BT*DD];
__device__ float g_scores[(size_t)ZZ*TT*TT];
__device__ float g_ctx[BT*DD];
__device__ float g_attnout[BT*DD];
__device__ float g_hmid[BT*DD];
__device__ float g_ffn1[(size_t)BT*FF];
__device__ float g_ffn2[BT*DD];

__device__ __forceinline__ float f2tf(float x) {
    unsigned r;
    asm("cvt.rna.tf32.f32 %0, %1;" : "=r"(r) : "f"(x));
    return __uint_as_float(r);
}

// =============== tf32 tensor-core GEMM (register-staged double buffer) ===============
// C[M,N] = A[M,K] @ op(B),  A row-major (lda), C row-major (ldc).
// BNT=true:  B stored [N,K] row-major -> C = A @ B^T  (weights, scores)
// BNT=false: B stored [K,N] row-major -> C = A @ B    (ctx = attn @ v)
// FUSE3: blockIdx.z in {0,1,2} selects (Bg,Cg)/(B1g,C1g)/(B2g,C2g) [QKV]
template<int BM, int BN, int WARPS_M, int WARPS_N, bool BNT, bool FUSE3>
__global__ __launch_bounds__(WARPS_M*WARPS_N*32)
void mma_gemm(const float* __restrict__ Ag, const float* __restrict__ Bg,
              const float* __restrict__ B1g, const float* __restrict__ B2g,
              const float* __restrict__ bias, float* __restrict__ Cg,
              float* __restrict__ C1g, float* __restrict__ C2g,
              int K, int lda, int ldb, int ldc, int nheads,
              long sAb, long sAh, long sBb, long sBh, long sCb, long sCh,
              float scale, int act)
{
    constexpr int BK = 16;
    constexpr int NTHR = WARPS_M*WARPS_N*32;
    constexpr int WM = BM/WARPS_M, WN = BN/WARPS_N;
    constexpr int MI = WM/16, NI = WN/8;
    constexpr int AP = 20;                      // stride 20: conflict-free frag reads
    constexpr int BS0 = BNT ? BN : BK;
    constexpr int BS1 = BNT ? 20 : (BN + 8);    // NN stride%32==8: conflict-free

    __shared__ float As[2][BM][AP];
    __shared__ float Bs[2][BS0][BS1];

    const int z  = blockIdx.z;
    const int bb = z / nheads, hh = z % nheads;
    const float* A = Ag + (long)bb*sAb + (long)hh*sAh;
    const float* B;
    float*       C;
    if constexpr (FUSE3) {
        B = (z == 0) ? Bg : (z == 1) ? B1g : B2g;
        C = (z == 0) ? Cg : (z == 1) ? C1g : C2g;
    } else {
        B = Bg + (long)bb*sBb + (long)hh*sBh;
        C = Cg + (long)bb*sCb + (long)hh*sCh;
    }

    const int m0 = blockIdx.y * BM;
    const int n0 = blockIdx.x * BN;
    const int tid = threadIdx.x;
    const int warp = tid >> 5, lane = tid & 31;
    const int wm = warp % WARPS_M, wn = warp / WARPS_M;
    const int g = lane >> 2, tig = lane & 3;

    // --- staging loaders ---
    constexpr int AROWS = NTHR/4;               // rows per pass
    constexpr int A_IT = BM/AROWS;
    const int ar = tid >> 2;
    const int ak = (tid & 3) * 4;
    float4 pa[A_IT];

    constexpr int B_IT_NT = BN/AROWS;
    constexpr int BCOLS = BN/4;                 // NN: threads per k-row
    constexpr int BKR = NTHR/BCOLS;             // NN: k-rows per pass
    constexpr int B_IT_NN = BK/BKR;
    constexpr int B_IT = BNT ? B_IT_NT : B_IT_NN;
    const int bkr = tid / BCOLS;
    const int bnc = (tid % BCOLS) * 4;
    float4 pb[B_IT];

    auto fetchA = [&](int k0) {
#pragma unroll
        for (int i = 0; i < A_IT; i++)
            pa[i] = *(const float4*)(A + (size_t)(m0 + ar + i*AROWS)*lda + k0 + ak);
    };
    auto fetchB = [&](int k0) {
        if constexpr (BNT) {
#pragma unroll
            for (int i = 0; i < B_IT; i++)
                pb[i] = *(const float4*)(B + (size_t)(n0 + ar + i*AROWS)*ldb + k0 + ak);
        } else {
#pragma unroll
            for (int i = 0; i < B_IT; i++)
                pb[i] = *(const float4*)(B + (size_t)(k0 + bkr + i*BKR)*ldb + n0 + bnc);
        }
    };
    auto stage = [&](int buf) {
#pragma unroll
        for (int i = 0; i < A_IT; i++) {
            float* d = &As[buf][ar + i*AROWS][ak];
            d[0] = f2tf(pa[i].x); d[1] = f2tf(pa[i].y);
            d[2] = f2tf(pa[i].z); d[3] = f2tf(pa[i].w);
        }
        if constexpr (BNT) {
#pragma unroll
            for (int i = 0; i < B_IT; i++) {
                float* d = &Bs[buf][ar + i*AROWS][ak];
                d[0] = f2tf(pb[i].x); d[1] = f2tf(pb[i].y);
                d[2] = f2tf(pb[i].z); d[3] = f2tf(pb[i].w);
            }
        } else {
#pragma unroll
            for (int i = 0; i < B_IT; i++) {
                float* d = &Bs[buf][bkr + i*BKR][bnc];
                d[0] = f2tf(pb[i].x); d[1] = f2tf(pb[i].y);
                d[2] = f2tf(pb[i].z); d[3] = f2tf(pb[i].w);
            }
        }
    };

    float acc[MI][NI][4];
#pragma unroll
    for (int mi = 0; mi < MI; mi++)
#pragma unroll
        for (int ni = 0; ni < NI; ni++)
#pragma unroll
            for (int r = 0; r < 4; r++) acc[mi][ni][r] = 0.f;

    auto compute = [&](int buf) {
#pragma unroll
        for (int kk = 0; kk < BK; kk += 8) {
            unsigned af[MI][4];
#pragma unroll
            for (int mi = 0; mi < MI; mi++) {
                int am = wm*WM + mi*16;
                af[mi][0] = __float_as_uint(As[buf][am + g    ][kk + tig    ]);
                af[mi][1] = __float_as_uint(As[buf][am + g + 8][kk + tig    ]);
                af[mi][2] = __float_as_uint(As[buf][am + g    ][kk + tig + 4]);
                af[mi][3] = __float_as_uint(As[buf][am + g + 8][kk + tig + 4]);
            }
            unsigned bf[NI][2];
#pragma unroll
            for (int ni = 0; ni < NI; ni++) {
                int bn = wn*WN + ni*8;
                if constexpr (BNT) {
                    bf[ni][0] = __float_as_uint(Bs[buf][bn + g][kk + tig    ]);
                    bf[ni][1] = __float_as_uint(Bs[buf][bn + g][kk + tig + 4]);
                } else {
                    bf[ni][0] = __float_as_uint(Bs[buf][kk + tig    ][bn + g]);
                    bf[ni][1] = __float_as_uint(Bs[buf][kk + tig + 4][bn + g]);
                }
            }
#pragma unroll
            for (int mi = 0; mi < MI; mi++)
#pragma unroll
                for (int ni = 0; ni < NI; ni++)
                    asm volatile(
                        "mma.sync.aligned.m16n8k8.row.col.f32.tf32.tf32.f32 "
                        "{%0,%1,%2,%3},{%4,%5,%6,%7},{%8,%9},{%0,%1,%2,%3};"
                        : "+f"(acc[mi][ni][0]), "+f"(acc[mi][ni][1]),
                          "+f"(acc[mi][ni][2]), "+f"(acc[mi][ni][3])
                        : "r"(af[mi][0]), "r"(af[mi][1]), "r"(af[mi][2]), "r"(af[mi][3]),
                          "r"(bf[ni][0]), "r"(bf[ni][1]));
        }
    };

    fetchA(0); fetchB(0);
    stage(0);
    __syncthreads();
    int buf = 0;
    const int nk = K / BK;
    for (int it = 1; it < nk; it++) {
        fetchA(it*BK); fetchB(it*BK);
        compute(buf);
        stage(buf ^ 1);
        __syncthreads();
        buf ^= 1;
    }
    compute(buf);

    // --- epilogue ---
#pragma unroll
    for (int mi = 0; mi < MI; mi++) {
        int row0 = m0 + wm*WM + mi*16 + g;
#pragma unroll
        for (int ni = 0; ni < NI; ni++) {
            int col = n0 + wn*WN + ni*8 + tig*2;
            float c0 = acc[mi][ni][0]*scale, c1 = acc[mi][ni][1]*scale;
            float c2 = acc[mi][ni][2]*scale, c3 = acc[mi][ni][3]*scale;
            if (bias) {
                float b0 = bias[col], b1 = bias[col+1];
                c0 += b0; c1 += b1; c2 += b0; c3 += b1;
            }
            if (act) {
                c0 = 0.5f*c0*(1.f + erff(c0*0.70710678118654752f));
                c1 = 0.5f*c1*(1.f + erff(c1*0.70710678118654752f));
                c2 = 0.5f*c2*(1.f + erff(c2*0.70710678118654752f));
                c3 = 0.5f*c3*(1.f + erff(c3*0.70710678118654752f));
            }
            *(float2*)&C[(size_t)row0*ldc + col]      = make_float2(c0, c1);
            *(float2*)&C[(size_t)(row0+8)*ldc + col]  = make_float2(c2, c3);
        }
    }
}

// ---------------- stage 1: h_base + language distribution p ----------------
__global__ void embed_base_kernel(const int* __restrict__ ids,
                                  const float* __restrict__ tok,
                                  const float* __restrict__ pos,
                                  const float* __restrict__ proto,
                                  const float* __restrict__ log_tau) {
    int row = blockIdx.x;
    int t = row % TT;
    int id = ids[row];
    const float* trow = tok + (size_t)id * DD;
    const float* prow = pos + (size_t)t * DD;
    float a0 = 0.f, a1 = 0.f;
    __shared__ float r0[256], r1[256];
    for (int d = threadIdx.x; d < DD; d += 256) {
        float v = trow[d] + prow[d];
        g_hbase[(size_t)row*DD + d] = v;
        a0 += v * proto[d];
        a1 += v * proto[DD + d];
    }
    r0[threadIdx.x] = a0; r1[threadIdx.x] = a1;
    __syncthreads();
    for (int s = 128; s > 0; s >>= 1) {
        if (threadIdx.x < s) {
            r0[threadIdx.x] += r0[threadIdx.x + s];
            r1[threadIdx.x] += r1[threadIdx.x + s];
        }
        __syncthreads();
    }
    if (threadIdx.x == 0) {
        float tau = fmaxf(expf(log_tau[0]), 0.25f);
        float l0 = r0[0] / tau, l1 = r1[0] / tau;
        float m = fmaxf(l0, l1);
        float e0 = expf(l0 - m), e1 = expf(l1 - m);
        float inv = 1.f / (e0 + e1);
        g_p[row*2 + 0] = e0 * inv;
        g_p[row*2 + 1] = e1 * inv;
    }
}

__global__ void switch_kernel() {
    int i = blockIdx.x * blockDim.x + threadIdx.x;
    if (i >= BT) return;
    int t = i % TT;
    float sv = 0.f;
    if (t > 0)
        sv = 1.f - (g_p[i*2]*g_p[(i-1)*2] + g_p[i*2+1]*g_p[(i-1)*2+1]);
    g_s[i] = sv;
}

__global__ void embed_ln_kernel(const float* __restrict__ lang,
                                const float* __restrict__ sw,
                                const float* __restrict__ w,
                                const float* __restrict__ b) {
    int row = blockIdx.x;
    __shared__ float xs[DD];
    __shared__ float rs[256], rq[256];
    float p0 = g_p[row*2], p1 = g_p[row*2+1], sv = g_s[row];
    float sum = 0.f, sq = 0.f;
    for (int d = threadIdx.x; d < DD; d += 256) {
        float x = g_hbase[(size_t)row*DD + d] + p0*lang[d] + p1*lang[DD+d] + sv*sw[d];
        xs[d] = x; sum += x; sq += x*x;
    }
    rs[threadIdx.x] = sum; rq[threadIdx.x] = sq;
    __syncthreads();
    for (int s = 128; s > 0; s >>= 1) {
        if (threadIdx.x < s) { rs[threadIdx.x]+=rs[threadIdx.x+s]; rq[threadIdx.x]+=rq[threadIdx.x+s]; }
        __syncthreads();
    }
    float mu = rs[0] * (1.f/DD);
    float var = rq[0] * (1.f/DD) - mu*mu;
    float rstd = rsqrtf(var + 1e-12f);
    for (int d = threadIdx.x; d < DD; d += 256)
        g_h[(size_t)row*DD + d] = (xs[d]-mu)*rstd*w[d] + b[d];
}

__global__ void ln_residual_kernel(const float* __restrict__ a,
                                   const float* __restrict__ bres,
                                   const float* __restrict__ w,
                                   const float* __restrict__ bias,
                                   float* __restrict__ out) {
    int row = blockIdx.x;
    __shared__ float xs[DD];
    __shared__ float rs[256], rq[256];
    float sum = 0.f, sq = 0.f;
    for (int d = threadIdx.x; d < DD; d += 256) {
        float x = a[(size_t)row*DD + d] + bres[(size_t)row*DD + d];
        xs[d] = x; sum += x; sq += x*x;
    }
    rs[threadIdx.x] = sum; rq[threadIdx.x] = sq;
    __syncthreads();
    for (int s = 128; s > 0; s >>= 1) {
        if (threadIdx.x < s) { rs[threadIdx.x]+=rs[threadIdx.x+s]; rq[threadIdx.x]+=rq[threadIdx.x+s]; }
        __syncthreads();
    }
    float mu = rs[0] * (1.f/DD);
    float var = rq[0] * (1.f/DD) - mu*mu;
    float rstd = rsqrtf(var + 1e-12f);
    for (int d = threadIdx.x; d < DD; d += 256)
        out[(size_t)row*DD + d] = (xs[d]-mu)*rstd*w[d] + bias[d];
}

// ---------------- bias + mask + softmax (in place over g_scores rows) ----------------
__global__ void __launch_bounds__(128) softmax_kernel(const float* __restrict__ compat_l,
                                                      const float* __restrict__ gamma_l,
                                                      const int* __restrict__ mask) {
    int idx = blockIdx.x;         // z*T + i
    int z = idx / TT; int i = idx % TT;
    int b = z / HH; int h = z % HH;
    float* row = g_scores + (size_t)idx * TT;
    float pi0 = g_p[(b*TT+i)*2], pi1 = g_p[(b*TT+i)*2+1];
    const float* C = compat_l + h*4;
    float cp0 = pi0*C[0] + pi1*C[2];
    float cp1 = pi0*C[1] + pi1*C[3];
    float gm = gamma_l[0];
    int tid = threadIdx.x;
    // vectorized: thread handles 4 consecutive j at tid*4
    int j0 = tid * 4;
    int gj0 = b*TT + j0;
    float4 rv = *(const float4*)(row + j0);
    float vals[4] = {rv.x, rv.y, rv.z, rv.w};
    const int4 mk = *(const int4*)(mask + gj0);
    const float4 pA = *(const float4*)(g_p + gj0*2);       // p[j0], p[j0+1]
    const float4 pB = *(const float4*)(g_p + gj0*2 + 4);   // p[j0+2], p[j0+3]
    const float4 sj = *(const float4*)(g_s + gj0);
    vals[0] += cp0*pA.x + cp1*pA.y + gm*sj.x + (1.f - (float)mk.x) * -10000.f;
    vals[1] += cp0*pA.z + cp1*pA.w + gm*sj.y + (1.f - (float)mk.y) * -10000.f;
    vals[2] += cp0*pB.x + cp1*pB.y + gm*sj.z + (1.f - (float)mk.z) * -10000.f;
    vals[3] += cp0*pB.z + cp1*pB.w + gm*sj.w + (1.f - (float)mk.w) * -10000.f;
    float mx = fmaxf(fmaxf(vals[0], vals[1]), fmaxf(vals[2], vals[3]));
    __shared__ float smax[4], ssum[4];
#pragma unroll
    for (int o = 16; o > 0; o >>= 1) mx = fmaxf(mx, __shfl_xor_sync(0xffffffffu, mx, o));
    if ((tid & 31) == 0) smax[tid >> 5] = mx;
    __syncthreads();
    mx = fmaxf(fmaxf(smax[0], smax[1]), fmaxf(smax[2], smax[3]));
    float sum = 0.f;
#pragma unroll
    for (int jj = 0; jj < 4; jj++) { vals[jj] = expf(vals[jj] - mx); sum += vals[jj]; }
#pragma unroll
    for (int o = 16; o > 0; o >>= 1) sum += __shfl_xor_sync(0xffffffffu, sum, o);
    if ((tid & 31) == 0) ssum[tid >> 5] = sum;
    __syncthreads();
    float inv = 1.f / (ssum[0] + ssum[1] + ssum[2] + ssum[3]);
    *(float4*)(row + j0) = make_float4(vals[0]*inv, vals[1]*inv, vals[2]*inv, vals[3]*inv);
}

// ---------------- host launch ----------------
extern "C" void kernel_launch(void* const* d_in, const int* in_sizes, int n_in,
                              void* d_out, int out_size) {
    const int*   ids      = (const int*)  d_in[0];
    const int*   mask     = (const int*)  d_in[1];
    const float* tok      = (const float*)d_in[2];
    const float* pos      = (const float*)d_in[3];
    const float* lang     = (const float*)d_in[4];
    const float* sw       = (const float*)d_in[5];
    const float* proto    = (const float*)d_in[6];
    const float* log_tau  = (const float*)d_in[7];
    const float* eln_w    = (const float*)d_in[8];
    const float* eln_b    = (const float*)d_in[9];
    const float* Wq       = (const float*)d_in[10];
    const float* Wk       = (const float*)d_in[11];
    const float* Wv       = (const float*)d_in[12];
    const float* Wo       = (const float*)d_in[13];
    const float* Wob      = (const float*)d_in[14];
    const float* compat   = (const float*)d_in[15];
    const float* gamma    = (const float*)d_in[16];
    const float* W1       = (const float*)d_in[17];
    const float* b1       = (const float*)d_in[18];
    const float* W2       = (const float*)d_in[19];
    const float* b2       = (const float*)d_in[20];
    const float* ln1w     = (const float*)d_in[21];
    const float* ln1b     = (const float*)d_in[22];
    const float* ln2w     = (const float*)d_in[23];
    const float* ln2b     = (const float*)d_in[24];
    float* out = (float*)d_out;

    float *h, *q, *k, *v, *scores, *ctx, *attnout, *hmid, *ffn1, *ffn2;
    cudaGetSymbolAddress((void**)&h,       g_h);
    cudaGetSymbolAddress((void**)&q,       g_q);
    cudaGetSymbolAddress((void**)&k,       g_k);
    cudaGetSymbolAddress((void**)&v,       g_v);
    cudaGetSymbolAddress((void**)&scores,  g_scores);
    cudaGetSymbolAddress((void**)&ctx,     g_ctx);
    cudaGetSymbolAddress((void**)&attnout, g_attnout);
    cudaGetSymbolAddress((void**)&hmid,    g_hmid);
    cudaGetSymbolAddress((void**)&ffn1,    g_ffn1);
    cudaGetSymbolAddress((void**)&ffn2,    g_ffn2);

    embed_base_kernel<<<BT, 256>>>(ids, tok, pos, proto, log_tau);
    switch_kernel<<<(BT + 255)/256, 256>>>();
    embed_ln_kernel<<<BT, 256>>>(lang, sw, eln_w, eln_b);

    const dim3 gQKV(DD/128, BT/128, 3);         // 6 x 32 x 3 = 576
    const dim3 gDense(DD/128, BT/128, 1);       // 6 x 32
    const dim3 gFfn1(FF/128, BT/128, 1);        // 24 x 32
    const dim3 gScores(TT/128, TT/128, ZZ);     // 4 x 4 x 96
    const dim3 gCtx(DHH/64, TT/128, ZZ);        // 1 x 4 x 96

    for (int l = 0; l < LL; l++) {
        const size_t wdd = (size_t)l * DD * DD;
        // fused QKV: blockIdx.z selects (Wq->q, Wk->k, Wv->v); 64x64 warp tiles
        mma_gemm<128,128,2,2,true,true><<<gQKV, 128>>>(h, Wq + wdd, Wk + wdd, Wv + wdd,
            nullptr, q, k, v,
            DD, DD, DD, DD, 1, 0,0,0,0,0,0, 1.f, 0);

        // scores[z] = (q_bh @ k_bh^T) * 0.125
        mma_gemm<128,128,2,2,true,false><<<gScores, 128>>>(q, k, nullptr, nullptr,
            nullptr, scores, nullptr, nullptr,
            DHH, DD, DD, TT, HH,
            (long)TT*DD, DHH, (long)TT*DD, DHH,
            (long)HH*TT*TT, (long)TT*TT, 0.125f, 0);

        softmax_kernel<<<ZZ*TT, 128>>>(compat + (size_t)l*HH*4, gamma + l, mask);

        // ctx[z] = attn[z] @ v_bh
        mma_gemm<128,64,4,2,false,false><<<gCtx, 256>>>(scores, v, nullptr, nullptr,
            nullptr, ctx, nullptr, nullptr,
            TT, TT, DD, DD, HH,
            (long)HH*TT*TT, (long)TT*TT, (long)TT*DD, DHH,
            (long)TT*DD, DHH, 1.f, 0);

        // Wo
        mma_gemm<128,128,2,2,true,false><<<gDense, 128>>>(ctx, Wo + wdd, nullptr, nullptr,
            Wob + (size_t)l*DD, attnout, nullptr, nullptr,
            DD, DD, DD, DD, 1, 0,0,0,0,0,0, 1.f, 0);
        ln_residual_kernel<<<BT, 256>>>(h, attnout, ln1w + (size_t)l*DD, ln1b + (size_t)l*DD, hmid);

        // FFN
        mma_gemm<128,128,2,2,true,false><<<gFfn1, 128>>>(hmid, W1 + (size_t)l*FF*DD, nullptr, nullptr,
            b1 + (size_t)l*FF, ffn1, nullptr, nullptr,
            DD, DD, DD, FF, 1, 0,0,0,0,0,0, 1.f, 1);
        mma_gemm<128,128,2,2,true,false><<<gDense, 128>>>(ffn1, W2 + (size_t)l*DD*FF, nullptr, nullptr,
            b2 + (size_t)l*DD, ffn2, nullptr, nullptr,
            FF, FF, FF, DD, 1, 0,0,0,0,0,0, 1.f, 0);

        float* hout = (l == LL-1) ? out : h;
        ln_residual_kernel<<<BT, 256>>>(hmid, ffn2, ln2w + (size_t)l*DD, ln2b + (size_t)l*DD, hout);
    }
}